// round 15
// baseline (speedup 1.0000x reference)
#include <cuda_runtime.h>
#include <cuda_fp16.h>
#include <cstdint>

#define BATCH 8
#define SEQ   2048
#define CDIM  1024
#define HDIM  64

// ---------------- persistent scratch ----------------
__device__ __half g_wth[3 * HDIM * CDIM];          // [192 n][1024 k] fp16 W^T
__device__ __half g_qh[BATCH * SEQ * HDIM];        // q PRE-SCALED by 0.125*log2(e)
__device__ __half g_kh[BATCH * SEQ * HDIM];
__device__ __half g_vh[BATCH * SEQ * HDIM];
__device__ float  g_partO[4][BATCH * SEQ * HDIM];
__device__ float  g_partL[4][BATCH * SEQ];
__device__ unsigned g_cnt[BATCH * 16];             // per-(b,qt) arrival counters

#define QSCALE 0.18033688011112042f   /* 0.125 * log2(e) */
#define ONESH2 0x3C003C00u            /* {1.0h, 1.0h}     */

// ---------------- helpers ----------------
__device__ __forceinline__ uint32_t smem_u32(const void* p) {
    uint32_t a;
    asm("{ .reg .u64 t; cvta.to.shared.u64 t, %1; cvt.u32.u64 %0, t; }" : "=r"(a) : "l"(p));
    return a;
}
__device__ __forceinline__ void cp16(uint32_t dst, const void* src) {
    asm volatile("cp.async.cg.shared.global [%0], [%1], 16;" :: "r"(dst), "l"(src));
}
#define CP_COMMIT asm volatile("cp.async.commit_group;" ::: "memory")
#define CP_WAIT0  asm volatile("cp.async.wait_group 0;" ::: "memory")

__device__ __forceinline__ uint32_t packh2(float lo, float hi) {
    uint32_t d;
    asm("cvt.rn.f16x2.f32 %0, %1, %2;" : "=r"(d) : "f"(hi), "f"(lo));
    return d;
}
__device__ __forceinline__ uint32_t ex2h2(uint32_t x) {
    uint32_t d;
    asm("ex2.approx.f16x2 %0, %1;" : "=r"(d) : "r"(x));
    return d;
}
__device__ __forceinline__ void mma16(float* c, const uint32_t* a, uint32_t b0, uint32_t b1) {
    asm volatile(
        "mma.sync.aligned.m16n8k16.row.col.f32.f16.f16.f32 "
        "{%0,%1,%2,%3}, {%4,%5,%6,%7}, {%8,%9}, {%0,%1,%2,%3};"
        : "+f"(c[0]), "+f"(c[1]), "+f"(c[2]), "+f"(c[3])
        : "r"(a[0]), "r"(a[1]), "r"(a[2]), "r"(a[3]), "r"(b0), "r"(b1));
}
__device__ __forceinline__ void ldm4(uint32_t* r, uint32_t addr) {
    asm volatile("ldmatrix.sync.aligned.m8n8.x4.shared.b16 {%0,%1,%2,%3}, [%4];"
                 : "=r"(r[0]), "=r"(r[1]), "=r"(r[2]), "=r"(r[3]) : "r"(addr));
}
__device__ __forceinline__ void ldm4t(uint32_t* r, uint32_t addr) {
    asm volatile("ldmatrix.sync.aligned.m8n8.x4.trans.shared.b16 {%0,%1,%2,%3}, [%4];"
                 : "=r"(r[0]), "=r"(r[1]), "=r"(r[2]), "=r"(r[3]) : "r"(addr));
}

// ================= Kernel 0: W transpose + fp16 =================
__global__ void wt_kernel(const float* __restrict__ Wq,
                          const float* __restrict__ Wk,
                          const float* __restrict__ Wv)
{
    const float* W = (blockIdx.z == 0) ? Wq : (blockIdx.z == 1) ? Wk : Wv;
    __shared__ float tile[32][33];
    int c0 = blockIdx.x * 32, h0 = blockIdx.y * 32;
    tile[threadIdx.y][threadIdx.x] = W[(size_t)(c0 + threadIdx.y) * HDIM + h0 + threadIdx.x];
    __syncthreads();
    g_wth[(size_t)blockIdx.z * HDIM * CDIM + (size_t)(h0 + threadIdx.y) * CDIM + c0 + threadIdx.x] =
        __float2half_rn(tile[threadIdx.x][threadIdx.y]);
}

// ================= Kernel 1: fused QKV projection =================
// grid 256 x 256 thr, 2 CTAs/SM. 64-row M-tile, K-chunk 64, double-buffered.
// SMEM words: A0[64*36]@0  A1@2304  B0[192*36]@4608  B1@11520  -> 73728 B
#define QKV_SMEM_BYTES 73728

__global__ void __launch_bounds__(256, 2) qkv_mma(const float* __restrict__ x)
{
    extern __shared__ uint32_t smw[];
    const uint32_t sb = smem_u32(smw);
    const int t = threadIdx.x, lane = t & 31, warp = t >> 5;
    const int g = lane >> 2, t4 = lane & 3;
    const int wm = warp >> 2, wn = warp & 3;           // 2M x 4N warps
    const int Mbase = blockIdx.x * 64;

    const uint32_t arow = lane & 15;
    const uint32_t asel = (uint32_t)((lane >> 4) << 4);
    const uint32_t nrow = (uint32_t)(((lane >> 4) << 3) + (lane & 7));
    const uint32_t bsel = (uint32_t)(((lane >> 3) & 1) << 4);

    float acc[2][6][4];
#pragma unroll
    for (int a = 0; a < 2; a++)
#pragma unroll
        for (int b = 0; b < 6; b++)
#pragma unroll
            for (int c = 0; c < 4; c++) acc[a][b][c] = 0.0f;

    const int xr = t >> 2, xj = t & 3;

    auto ldgX = [&](int c, float4* v) {
        const float* src = x + (size_t)(Mbase + xr) * CDIM + c * 64 + xj * 16;
#pragma unroll
        for (int i = 0; i < 4; i++) v[i] = *reinterpret_cast<const float4*>(src + i * 4);
    };
    auto stsX = [&](int st, const float4* v) {
        uint4 h0, h1;
        h0.x = packh2(v[0].x, v[0].y); h0.y = packh2(v[0].z, v[0].w);
        h0.z = packh2(v[1].x, v[1].y); h0.w = packh2(v[1].z, v[1].w);
        h1.x = packh2(v[2].x, v[2].y); h1.y = packh2(v[2].z, v[2].w);
        h1.z = packh2(v[3].x, v[3].y); h1.w = packh2(v[3].z, v[3].w);
        *reinterpret_cast<uint4*>(smw + st * 2304 + xr * 36 + xj * 8)     = h0;
        *reinterpret_cast<uint4*>(smw + st * 2304 + xr * 36 + xj * 8 + 4) = h1;
    };
    auto issueB = [&](int c, int st) {
        uint32_t bb = sb + (4608u + (uint32_t)st * 6912u) * 4u;
#pragma unroll
        for (int i = 0; i < 6; i++) {
            int idx = t + i * 256;
            int n = idx >> 3, j = idx & 7;
            cp16(bb + (uint32_t)(n * 36 + j * 4) * 4u,
                 g_wth + (size_t)n * CDIM + c * 64 + j * 8);
        }
    };

    float4 xa[4];
    ldgX(0, xa); stsX(0, xa);
    issueB(0, 0); CP_COMMIT;

    for (int c = 0; c < 16; c++) {
        const int st = c & 1;
        CP_WAIT0;
        __syncthreads();
        if (c < 15) { issueB(c + 1, st ^ 1); CP_COMMIT; ldgX(c + 1, xa); }

        const uint32_t Ab = sb + (uint32_t)st * 2304u * 4u;
        const uint32_t Bb = sb + (4608u + (uint32_t)st * 6912u) * 4u;

#pragma unroll
        for (int kk = 0; kk < 4; kk++) {
            uint32_t af0[4], af1[4];
            ldm4(af0, Ab + (wm * 32 +      arow) * 144u + kk * 32u + asel);
            ldm4(af1, Ab + (wm * 32 + 16 + arow) * 144u + kk * 32u + asel);
#pragma unroll
            for (int j = 0; j < 3; j++) {
                uint32_t bf[4];
                ldm4(bf, Bb + (wn * 48 + j * 16 + nrow) * 144u + kk * 32u + bsel);
                mma16(acc[0][2 * j],     af0, bf[0], bf[1]);
                mma16(acc[0][2 * j + 1], af0, bf[2], bf[3]);
                mma16(acc[1][2 * j],     af1, bf[0], bf[1]);
                mma16(acc[1][2 * j + 1], af1, bf[2], bf[3]);
            }
        }
        if (c < 15) stsX(st ^ 1, xa);
    }

    // epilogue: q is pre-scaled by QSCALE (softmax scale folded into log2 domain)
#pragma unroll
    for (int mt = 0; mt < 2; mt++) {
        int r0 = Mbase + wm * 32 + mt * 16 + g;
#pragma unroll
        for (int nt = 0; nt < 6; nt++) {
            int ncol = wn * 48 + nt * 8 + 2 * t4;
            int w = ncol >> 6, cc = ncol & 63;
            __half* outp = (w == 0) ? g_qh : (w == 1) ? g_kh : g_vh;
            float sc = (w == 0) ? QSCALE : 1.0f;
            *reinterpret_cast<uint32_t*>(outp + (size_t)r0 * HDIM + cc) =
                packh2(acc[mt][nt][0] * sc, acc[mt][nt][1] * sc);
            *reinterpret_cast<uint32_t*>(outp + (size_t)(r0 + 8) * HDIM + cc) =
                packh2(acc[mt][nt][2] * sc, acc[mt][nt][3] * sc);
        }
    }
}

// ================= Kernel 2: split-K causal attention + in-kernel combine ====
// 272 CTAs (34/batch), max 5 key-tile iters, ONE wave at 2 CTAs/SM.
// ns(qt)=ceil((qt+1)/5). ns==1 (qt<=4) writes directly. ns>1: partials +
// last-arriver (threadfence/atomic counter) combines in fixed slot order.
// SMEM words: K0@0 K1@4608 V0@9216 V1@13824 Q@18432 (each 4608) -> 92160 B
#define ATTN_SMEM_BYTES 92160

__global__ void __launch_bounds__(256, 2) attn_split(float* __restrict__ outp)
{
    extern __shared__ uint32_t smw[];
    const uint32_t sb = smem_u32(smw);
    const int t = threadIdx.x, lane = t & 31, warp = t >> 5;
    const int g = lane >> 2, t4 = lane & 3;

    const int bid = blockIdx.x;
    const int b = bid / 34, r = bid % 34;
    int qt, s, ns;
    if (r < 5)        { qt = r;                 s = 0;            ns = 1; }
    else if (r < 15)  { qt = 5 + (r - 5) / 2;   s = (r - 5) % 2;  ns = 2; }
    else if (r < 30)  { qt = 10 + (r - 15) / 3; s = (r - 15) % 3; ns = 3; }
    else              { qt = 15;                s = r - 30;       ns = 4; }
    const int len = qt + 1;
    const int k0t = s * len / ns, k1t = (s + 1) * len / ns;
    const int qBase = qt * 128;

    const __half* kg = g_kh + (size_t)b * SEQ * HDIM;
    const __half* vg = g_vh + (size_t)b * SEQ * HDIM;

    const uint32_t lrow8 = (uint32_t)(((lane >> 4) << 3) + (lane & 7));
    const uint32_t lsel  = (uint32_t)(((lane >> 3) & 1) << 4);
    const uint32_t vrow  = (uint32_t)((((lane >> 3) & 1) << 3) + (lane & 7));
    const uint32_t vsel  = (uint32_t)((lane >> 4) << 4);

    auto issueKV = [&](int kt, int st) {
        uint32_t kb = sb + (uint32_t)st * 4608u * 4u;
        uint32_t vb = sb + (9216u + (uint32_t)st * 4608u) * 4u;
#pragma unroll
        for (int i = 0; i < 4; i++) {
            int idx = t + i * 256;
            int rr = idx >> 3, j = idx & 7;
            cp16(kb + (uint32_t)(rr * 36 + j * 4) * 4u,
                 kg + (size_t)(kt * 128 + rr) * HDIM + j * 8);
            cp16(vb + (uint32_t)(rr * 36 + j * 4) * 4u,
                 vg + (size_t)(kt * 128 + rr) * HDIM + j * 8);
        }
    };

    issueKV(k0t, 0);
    {
        const __half* qg = g_qh + ((size_t)b * SEQ + qBase) * HDIM;
#pragma unroll
        for (int i = 0; i < 4; i++) {
            int idx = t + i * 256;
            int rr = idx >> 3, j = idx & 7;
            cp16(sb + (uint32_t)(18432 + rr * 36 + j * 4) * 4u,
                 qg + (size_t)rr * HDIM + j * 8);
        }
    }
    CP_COMMIT;
    CP_WAIT0;
    __syncthreads();

    uint32_t qf[4][4];
    {
        const uint32_t Qb = sb + 18432u * 4u;
        const uint32_t qrow = (uint32_t)(warp * 16 + (lane & 15));
        const uint32_t qsel = (uint32_t)((lane >> 4) << 4);
#pragma unroll
        for (int kk = 0; kk < 4; kk++) ldm4(qf[kk], Qb + qrow * 144u + kk * 32u + qsel);
    }

    float oacc[8][4];
#pragma unroll
    for (int a = 0; a < 8; a++)
#pragma unroll
        for (int c = 0; c < 4; c++) oacc[a][c] = 0.0f;
    float lacc[4] = {0.0f, 0.0f, 0.0f, 0.0f};
    const int r0l = warp * 16 + g;

    for (int kt = k0t; kt < k1t; kt++) {
        const int st = (kt - k0t) & 1;
        const bool more = (kt + 1 < k1t);
        if (kt > k0t) { CP_WAIT0; __syncthreads(); }
        if (more) { issueKV(kt + 1, st ^ 1); CP_COMMIT; }

        const uint32_t Kb = sb + (uint32_t)st * 4608u * 4u;
        const uint32_t Vb = sb + (9216u + (uint32_t)st * 4608u) * 4u;
        const bool dtile = (kt == qt);

#pragma unroll
        for (int hl = 0; hl < 2; hl++) {
            // diagonal tile: warps 0-3 (queries 0-63) see only masked keys in hl=1
            if (dtile && hl == 1 && warp < 4) continue;

            // ---- S = Qs @ K^T (64-key half), already in log2 domain ----
            float sacc[8][4];
#pragma unroll
            for (int a = 0; a < 8; a++)
#pragma unroll
                for (int c = 0; c < 4; c++) sacc[a][c] = 0.0f;
#pragma unroll
            for (int p = 0; p < 4; p++) {
                const uint32_t krow = (uint32_t)(hl * 64 + p * 16) + lrow8;
#pragma unroll
                for (int kk = 0; kk < 4; kk++) {
                    uint32_t kb[4];
                    ldm4(kb, Kb + krow * 144u + kk * 32u + lsel);
                    mma16(sacc[2 * p],     qf[kk], kb[0], kb[1]);
                    mma16(sacc[2 * p + 1], qf[kk], kb[2], kb[3]);
                }
            }
            // ---- P = 2^S via f16x2 MUFU, mask on packed halves ----
            uint32_t pf01[8], pf23[8];
#pragma unroll
            for (int nt = 0; nt < 8; nt++) {
                uint32_t e01 = ex2h2(packh2(sacc[nt][0], sacc[nt][1]));
                uint32_t e23 = ex2h2(packh2(sacc[nt][2], sacc[nt][3]));
                if (dtile) {
                    int c0 = hl * 64 + nt * 8 + 2 * t4;
                    uint32_t m0 = (c0 <= r0l      ? 0x0000FFFFu : 0u) |
                                  (c0 + 1 <= r0l  ? 0xFFFF0000u : 0u);
                    uint32_t m1 = (c0 <= r0l + 8     ? 0x0000FFFFu : 0u) |
                                  (c0 + 1 <= r0l + 8 ? 0xFFFF0000u : 0u);
                    e01 &= m0; e23 &= m1;
                }
                pf01[nt] = e01; pf23[nt] = e23;
            }
            // ---- O += P @ V ; l += P @ ones (tensor-pipe row-sum) ----
#pragma unroll
            for (int kk = 0; kk < 4; kk++) {
                uint32_t af[4];
                af[0] = pf01[2 * kk];     af[1] = pf23[2 * kk];
                af[2] = pf01[2 * kk + 1]; af[3] = pf23[2 * kk + 1];
                mma16(lacc, af, ONESH2, ONESH2);
                const uint32_t vr = (uint32_t)(hl * 64 + kk * 16) + vrow;
#pragma unroll
                for (int p = 0; p < 4; p++) {
                    uint32_t vb[4];
                    ldm4t(vb, Vb + vr * 144u + (uint32_t)(p * 32) + vsel);
                    mma16(oacc[2 * p],     af, vb[0], vb[1]);
                    mma16(oacc[2 * p + 1], af, vb[2], vb[3]);
                }
            }
        }
    }

    // ---- epilogue: lacc[0]/lacc[2] hold complete row-sums in EVERY lane ----
    if (ns == 1) {
        const float inv0 = 1.0f / lacc[0];
        const float inv1 = 1.0f / lacc[2];
        float* og = outp + ((size_t)b * SEQ + qBase + r0l) * HDIM;
#pragma unroll
        for (int nt = 0; nt < 8; nt++) {
            int cc = nt * 8 + 2 * t4;
            float2 v0 = { oacc[nt][0] * inv0, oacc[nt][1] * inv0 };
            *reinterpret_cast<float2*>(og + cc) = v0;
            float2 v1 = { oacc[nt][2] * inv1, oacc[nt][3] * inv1 };
            *reinterpret_cast<float2*>(og + (size_t)8 * HDIM + cc) = v1;
        }
        return;
    }

    // ---- write partials ----
    float* po = g_partO[s] + ((size_t)b * SEQ + qBase + r0l) * HDIM;
#pragma unroll
    for (int nt = 0; nt < 8; nt++) {
        int cc = nt * 8 + 2 * t4;
        float2 v0 = { oacc[nt][0], oacc[nt][1] };
        *reinterpret_cast<float2*>(po + cc) = v0;
        float2 v1 = { oacc[nt][2], oacc[nt][3] };
        *reinterpret_cast<float2*>(po + (size_t)8 * HDIM + cc) = v1;
    }
    if (t4 == 0) {
        g_partL[s][(size_t)b * SEQ + qBase + r0l]     = lacc[0];
        g_partL[s][(size_t)b * SEQ + qBase + r0l + 8] = lacc[2];
    }

    // ---- last-arriver combine (threadFenceReduction pattern) ----
    __threadfence();
    __syncthreads();
    __shared__ unsigned sIsLast;
    if (t == 0) {
        unsigned old = atomicAdd(&g_cnt[b * 16 + qt], 1u);
        sIsLast = ((old % (unsigned)ns) == (unsigned)(ns - 1)) ? 1u : 0u;
    }
    __syncthreads();
    if (!sIsLast) return;

    // deterministic: fixed slot order ss = 0..ns-1 (same as old combine kernel)
    const size_t rowBase = (size_t)b * SEQ + qBase;
#pragma unroll
    for (int i = 0; i < 8; i++) {
        int idx = t + i * 256;              // 0..2047 float4 within the 128x64 tile
        int row = idx >> 4;
        size_t f4i = (rowBase + row) * 16 + (idx & 15);
        float4 o = {0.0f, 0.0f, 0.0f, 0.0f};
        float  l = 0.0f;
#pragma unroll
        for (int ss = 0; ss < 4; ss++) {
            if (ss < ns) {
                float4 c = reinterpret_cast<const float4*>(g_partO[ss])[f4i];
                o.x += c.x; o.y += c.y; o.z += c.z; o.w += c.w;
                l += g_partL[ss][rowBase + row];
            }
        }
        float inv = 1.0f / l;
        o.x *= inv; o.y *= inv; o.z *= inv; o.w *= inv;
        reinterpret_cast<float4*>(outp)[f4i] = o;
    }
}

// ---------------- launch ----------------
extern "C" void kernel_launch(void* const* d_in, const int* in_sizes, int n_in,
                              void* d_out, int out_size)
{
    const float* x  = (const float*)d_in[0];
    const float* Wq = (const float*)d_in[1];
    const float* Wk = (const float*)d_in[2];
    const float* Wv = (const float*)d_in[3];
    float* out = (float*)d_out;

    wt_kernel<<<dim3(CDIM / 32, HDIM / 32, 3), dim3(32, 32)>>>(Wq, Wk, Wv);

    cudaFuncSetAttribute(qkv_mma, cudaFuncAttributeMaxDynamicSharedMemorySize,
                         QKV_SMEM_BYTES);
    qkv_mma<<<(BATCH * SEQ) / 64, 256, QKV_SMEM_BYTES>>>(x);

    cudaFuncSetAttribute(attn_split, cudaFuncAttributeMaxDynamicSharedMemorySize,
                         ATTN_SMEM_BYTES);
    attn_split<<<272, 256, ATTN_SMEM_BYTES>>>(out);
}

// round 16
// speedup vs baseline: 1.0115x; 1.0115x over previous
#include <cuda_runtime.h>
#include <cuda_fp16.h>
#include <cstdint>

#define BATCH 8
#define SEQ   2048
#define CDIM  1024
#define HDIM  64

// ---------------- persistent scratch ----------------
__device__ __half g_wth[3 * HDIM * CDIM];          // [192 n][1024 k] fp16 W^T
__device__ __half g_qh[BATCH * SEQ * HDIM];        // q PRE-SCALED by 0.125*log2(e)
__device__ __half g_kh[BATCH * SEQ * HDIM];
__device__ __half g_vh[BATCH * SEQ * HDIM];
__device__ float  g_partO[4][BATCH * SEQ * HDIM];
__device__ float  g_partL[4][BATCH * SEQ];

#define QSCALE 0.18033688011112042f   /* 0.125 * log2(e) */
#define ONESH2 0x3C003C00u            /* {1.0h, 1.0h}     */

// ---------------- helpers ----------------
__device__ __forceinline__ uint32_t smem_u32(const void* p) {
    uint32_t a;
    asm("{ .reg .u64 t; cvta.to.shared.u64 t, %1; cvt.u32.u64 %0, t; }" : "=r"(a) : "l"(p));
    return a;
}
__device__ __forceinline__ void cp16(uint32_t dst, const void* src) {
    asm volatile("cp.async.cg.shared.global [%0], [%1], 16;" :: "r"(dst), "l"(src));
}
#define CP_COMMIT asm volatile("cp.async.commit_group;" ::: "memory")
#define CP_WAIT0  asm volatile("cp.async.wait_group 0;" ::: "memory")
#define CP_WAIT1  asm volatile("cp.async.wait_group 1;" ::: "memory")

__device__ __forceinline__ uint32_t packh2(float lo, float hi) {
    uint32_t d;
    asm("cvt.rn.f16x2.f32 %0, %1, %2;" : "=r"(d) : "f"(hi), "f"(lo));
    return d;
}
__device__ __forceinline__ uint32_t ex2h2(uint32_t x) {
    uint32_t d;
    asm("ex2.approx.f16x2 %0, %1;" : "=r"(d) : "r"(x));
    return d;
}
__device__ __forceinline__ void mma16(float* c, const uint32_t* a, uint32_t b0, uint32_t b1) {
    asm volatile(
        "mma.sync.aligned.m16n8k16.row.col.f32.f16.f16.f32 "
        "{%0,%1,%2,%3}, {%4,%5,%6,%7}, {%8,%9}, {%0,%1,%2,%3};"
        : "+f"(c[0]), "+f"(c[1]), "+f"(c[2]), "+f"(c[3])
        : "r"(a[0]), "r"(a[1]), "r"(a[2]), "r"(a[3]), "r"(b0), "r"(b1));
}
__device__ __forceinline__ void ldm4(uint32_t* r, uint32_t addr) {
    asm volatile("ldmatrix.sync.aligned.m8n8.x4.shared.b16 {%0,%1,%2,%3}, [%4];"
                 : "=r"(r[0]), "=r"(r[1]), "=r"(r[2]), "=r"(r[3]) : "r"(addr));
}
__device__ __forceinline__ void ldm4t(uint32_t* r, uint32_t addr) {
    asm volatile("ldmatrix.sync.aligned.m8n8.x4.trans.shared.b16 {%0,%1,%2,%3}, [%4];"
                 : "=r"(r[0]), "=r"(r[1]), "=r"(r[2]), "=r"(r[3]) : "r"(addr));
}

// ================= Kernel 0: W transpose + fp16 (MLP-optimized) =================
// grid (16, 3) x 256 thr: 64c x 64n tile per block. 4 float4 LDG + 2 uint4 STG
// per thread, transpose through a 64x65 smem tile.
__global__ void __launch_bounds__(256) wt_kernel(const float* __restrict__ Wq,
                                                 const float* __restrict__ Wk,
                                                 const float* __restrict__ Wv)
{
    const int z = blockIdx.y;
    const float* W = (z == 0) ? Wq : (z == 1) ? Wk : Wv;
    __shared__ float tile[64][65];
    const int t = threadIdx.x;
    const int c0 = blockIdx.x * 64;

    // load 64 rows x 64 cols (rows = c, cols = n), coalesced float4
#pragma unroll
    for (int i = 0; i < 4; i++) {
        int idx = t + i * 256;          // 0..1023 float4
        int r = idx >> 4, q = idx & 15;
        float4 v = *reinterpret_cast<const float4*>(W + (size_t)(c0 + r) * HDIM + q * 4);
        tile[r][q * 4 + 0] = v.x; tile[r][q * 4 + 1] = v.y;
        tile[r][q * 4 + 2] = v.z; tile[r][q * 4 + 3] = v.w;
    }
    __syncthreads();

    // write transposed: g_wth[n][c], 8 consecutive c per uint4 (8 fp16)
    __half* outp = g_wth + (size_t)z * HDIM * CDIM;
#pragma unroll
    for (int i = 0; i < 2; i++) {
        int idx = t + i * 256;          // 0..511 groups
        int n = idx >> 3, cg = idx & 7;
        uint4 h;
        h.x = packh2(tile[cg * 8 + 0][n], tile[cg * 8 + 1][n]);
        h.y = packh2(tile[cg * 8 + 2][n], tile[cg * 8 + 3][n]);
        h.z = packh2(tile[cg * 8 + 4][n], tile[cg * 8 + 5][n]);
        h.w = packh2(tile[cg * 8 + 6][n], tile[cg * 8 + 7][n]);
        *reinterpret_cast<uint4*>(outp + (size_t)n * CDIM + c0 + cg * 8) = h;
    }
}

// ================= Kernel 1: fused QKV projection (3-stage pipeline) =========
// grid 256 x 256 thr, 2 CTAs/SM. 64-row M-tile, K-chunk 64, 3-stage ring with
// prefetch distance 2 (wait_group 1) -> B-tile L2 latency fully hidden.
// SMEM words: A0@0 A1@2304 A2@4608  B0@6912 B1@13824 B2@20736 -> 110592 B
#define QKV_SMEM_BYTES 110592

__global__ void __launch_bounds__(256, 2) qkv_mma(const float* __restrict__ x)
{
    extern __shared__ uint32_t smw[];
    const uint32_t sb = smem_u32(smw);
    const int t = threadIdx.x, lane = t & 31, warp = t >> 5;
    const int g = lane >> 2, t4 = lane & 3;
    const int wm = warp >> 2, wn = warp & 3;           // 2M x 4N warps
    const int Mbase = blockIdx.x * 64;

    const uint32_t arow = lane & 15;
    const uint32_t asel = (uint32_t)((lane >> 4) << 4);
    const uint32_t nrow = (uint32_t)(((lane >> 4) << 3) + (lane & 7));
    const uint32_t bsel = (uint32_t)(((lane >> 3) & 1) << 4);

    float acc[2][6][4];
#pragma unroll
    for (int a = 0; a < 2; a++)
#pragma unroll
        for (int b = 0; b < 6; b++)
#pragma unroll
            for (int c = 0; c < 4; c++) acc[a][b][c] = 0.0f;

    const int xr = t >> 2, xj = t & 3;

    auto ldgX = [&](int c, float4* v) {
        const float* src = x + (size_t)(Mbase + xr) * CDIM + c * 64 + xj * 16;
#pragma unroll
        for (int i = 0; i < 4; i++) v[i] = *reinterpret_cast<const float4*>(src + i * 4);
    };
    auto stsX = [&](int st, const float4* v) {
        uint4 h0, h1;
        h0.x = packh2(v[0].x, v[0].y); h0.y = packh2(v[0].z, v[0].w);
        h0.z = packh2(v[1].x, v[1].y); h0.w = packh2(v[1].z, v[1].w);
        h1.x = packh2(v[2].x, v[2].y); h1.y = packh2(v[2].z, v[2].w);
        h1.z = packh2(v[3].x, v[3].y); h1.w = packh2(v[3].z, v[3].w);
        *reinterpret_cast<uint4*>(smw + st * 2304 + xr * 36 + xj * 8)     = h0;
        *reinterpret_cast<uint4*>(smw + st * 2304 + xr * 36 + xj * 8 + 4) = h1;
    };
    auto issueB = [&](int c, int st) {
        uint32_t bb = sb + (6912u + (uint32_t)st * 6912u) * 4u;
#pragma unroll
        for (int i = 0; i < 6; i++) {
            int idx = t + i * 256;
            int n = idx >> 3, j = idx & 7;
            cp16(bb + (uint32_t)(n * 36 + j * 4) * 4u,
                 g_wth + (size_t)n * CDIM + c * 64 + j * 8);
        }
    };

    float4 xa[4];
    ldgX(0, xa); stsX(0, xa);
    ldgX(1, xa); stsX(1, xa);
    issueB(0, 0); CP_COMMIT;
    issueB(1, 1); CP_COMMIT;

    for (int c = 0; c < 16; c++) {
        const int st = c % 3;
        if (c < 15) { CP_WAIT1; } else { CP_WAIT0; }
        __syncthreads();
        if (c < 14) { issueB(c + 2, (c + 2) % 3); CP_COMMIT; ldgX(c + 2, xa); }

        const uint32_t Ab = sb + (uint32_t)st * 2304u * 4u;
        const uint32_t Bb = sb + (6912u + (uint32_t)st * 6912u) * 4u;

#pragma unroll
        for (int kk = 0; kk < 4; kk++) {
            uint32_t af0[4], af1[4];
            ldm4(af0, Ab + (wm * 32 +      arow) * 144u + kk * 32u + asel);
            ldm4(af1, Ab + (wm * 32 + 16 + arow) * 144u + kk * 32u + asel);
#pragma unroll
            for (int j = 0; j < 3; j++) {
                uint32_t bf[4];
                ldm4(bf, Bb + (wn * 48 + j * 16 + nrow) * 144u + kk * 32u + bsel);
                mma16(acc[0][2 * j],     af0, bf[0], bf[1]);
                mma16(acc[0][2 * j + 1], af0, bf[2], bf[3]);
                mma16(acc[1][2 * j],     af1, bf[0], bf[1]);
                mma16(acc[1][2 * j + 1], af1, bf[2], bf[3]);
            }
        }
        if (c < 14) stsX((c + 2) % 3, xa);             // readers of this stage done pre-sync
    }

    // epilogue: q is pre-scaled by QSCALE (softmax scale folded into log2 domain)
#pragma unroll
    for (int mt = 0; mt < 2; mt++) {
        int r0 = Mbase + wm * 32 + mt * 16 + g;
#pragma unroll
        for (int nt = 0; nt < 6; nt++) {
            int ncol = wn * 48 + nt * 8 + 2 * t4;
            int w = ncol >> 6, cc = ncol & 63;
            __half* outp = (w == 0) ? g_qh : (w == 1) ? g_kh : g_vh;
            float sc = (w == 0) ? QSCALE : 1.0f;
            *reinterpret_cast<uint32_t*>(outp + (size_t)r0 * HDIM + cc) =
                packh2(acc[mt][nt][0] * sc, acc[mt][nt][1] * sc);
            *reinterpret_cast<uint32_t*>(outp + (size_t)(r0 + 8) * HDIM + cc) =
                packh2(acc[mt][nt][2] * sc, acc[mt][nt][3] * sc);
        }
    }
}

// ================= Kernel 2: split-K causal attention =================
// 272 CTAs (34/batch), max 5 key-tile iters, ONE wave at 2 CTAs/SM.
// ns(qt)=ceil((qt+1)/5). ns==1 (qt<=4) writes normalized output directly.
// SMEM words: K0@0 K1@4608 V0@9216 V1@13824 Q@18432 (each 4608) -> 92160 B
#define ATTN_SMEM_BYTES 92160

__global__ void __launch_bounds__(256, 2) attn_split(float* __restrict__ outp)
{
    extern __shared__ uint32_t smw[];
    const uint32_t sb = smem_u32(smw);
    const int t = threadIdx.x, lane = t & 31, warp = t >> 5;
    const int g = lane >> 2, t4 = lane & 3;

    const int bid = blockIdx.x;
    const int b = bid / 34, r = bid % 34;
    int qt, s, ns;
    if (r < 5)        { qt = r;                 s = 0;            ns = 1; }
    else if (r < 15)  { qt = 5 + (r - 5) / 2;   s = (r - 5) % 2;  ns = 2; }
    else if (r < 30)  { qt = 10 + (r - 15) / 3; s = (r - 15) % 3; ns = 3; }
    else              { qt = 15;                s = r - 30;       ns = 4; }
    const int len = qt + 1;
    const int k0t = s * len / ns, k1t = (s + 1) * len / ns;
    const int qBase = qt * 128;

    const __half* kg = g_kh + (size_t)b * SEQ * HDIM;
    const __half* vg = g_vh + (size_t)b * SEQ * HDIM;

    const uint32_t lrow8 = (uint32_t)(((lane >> 4) << 3) + (lane & 7));
    const uint32_t lsel  = (uint32_t)(((lane >> 3) & 1) << 4);
    const uint32_t vrow  = (uint32_t)((((lane >> 3) & 1) << 3) + (lane & 7));
    const uint32_t vsel  = (uint32_t)((lane >> 4) << 4);

    auto issueKV = [&](int kt, int st) {
        uint32_t kb = sb + (uint32_t)st * 4608u * 4u;
        uint32_t vb = sb + (9216u + (uint32_t)st * 4608u) * 4u;
#pragma unroll
        for (int i = 0; i < 4; i++) {
            int idx = t + i * 256;
            int rr = idx >> 3, j = idx & 7;
            cp16(kb + (uint32_t)(rr * 36 + j * 4) * 4u,
                 kg + (size_t)(kt * 128 + rr) * HDIM + j * 8);
            cp16(vb + (uint32_t)(rr * 36 + j * 4) * 4u,
                 vg + (size_t)(kt * 128 + rr) * HDIM + j * 8);
        }
    };

    issueKV(k0t, 0);
    {
        const __half* qg = g_qh + ((size_t)b * SEQ + qBase) * HDIM;
#pragma unroll
        for (int i = 0; i < 4; i++) {
            int idx = t + i * 256;
            int rr = idx >> 3, j = idx & 7;
            cp16(sb + (uint32_t)(18432 + rr * 36 + j * 4) * 4u,
                 qg + (size_t)rr * HDIM + j * 8);
        }
    }
    CP_COMMIT;
    CP_WAIT0;
    __syncthreads();

    uint32_t qf[4][4];
    {
        const uint32_t Qb = sb + 18432u * 4u;
        const uint32_t qrow = (uint32_t)(warp * 16 + (lane & 15));
        const uint32_t qsel = (uint32_t)((lane >> 4) << 4);
#pragma unroll
        for (int kk = 0; kk < 4; kk++) ldm4(qf[kk], Qb + qrow * 144u + kk * 32u + qsel);
    }

    float oacc[8][4];
#pragma unroll
    for (int a = 0; a < 8; a++)
#pragma unroll
        for (int c = 0; c < 4; c++) oacc[a][c] = 0.0f;
    float lacc[4] = {0.0f, 0.0f, 0.0f, 0.0f};
    const int r0l = warp * 16 + g;

    for (int kt = k0t; kt < k1t; kt++) {
        const int st = (kt - k0t) & 1;
        const bool more = (kt + 1 < k1t);
        if (kt > k0t) { CP_WAIT0; __syncthreads(); }
        if (more) { issueKV(kt + 1, st ^ 1); CP_COMMIT; }

        const uint32_t Kb = sb + (uint32_t)st * 4608u * 4u;
        const uint32_t Vb = sb + (9216u + (uint32_t)st * 4608u) * 4u;
        const bool dtile = (kt == qt);

#pragma unroll
        for (int hl = 0; hl < 2; hl++) {
            // diagonal tile: warps 0-3 (queries 0-63) see only masked keys in hl=1
            if (dtile && hl == 1 && warp < 4) continue;

            // ---- S = Qs @ K^T (64-key half), already in log2 domain ----
            float sacc[8][4];
#pragma unroll
            for (int a = 0; a < 8; a++)
#pragma unroll
                for (int c = 0; c < 4; c++) sacc[a][c] = 0.0f;
#pragma unroll
            for (int p = 0; p < 4; p++) {
                const uint32_t krow = (uint32_t)(hl * 64 + p * 16) + lrow8;
#pragma unroll
                for (int kk = 0; kk < 4; kk++) {
                    uint32_t kb[4];
                    ldm4(kb, Kb + krow * 144u + kk * 32u + lsel);
                    mma16(sacc[2 * p],     qf[kk], kb[0], kb[1]);
                    mma16(sacc[2 * p + 1], qf[kk], kb[2], kb[3]);
                }
            }
            // ---- P = 2^S via f16x2 MUFU, mask on packed halves ----
            uint32_t pf01[8], pf23[8];
#pragma unroll
            for (int nt = 0; nt < 8; nt++) {
                uint32_t e01 = ex2h2(packh2(sacc[nt][0], sacc[nt][1]));
                uint32_t e23 = ex2h2(packh2(sacc[nt][2], sacc[nt][3]));
                if (dtile) {
                    int c0 = hl * 64 + nt * 8 + 2 * t4;
                    uint32_t m0 = (c0 <= r0l      ? 0x0000FFFFu : 0u) |
                                  (c0 + 1 <= r0l  ? 0xFFFF0000u : 0u);
                    uint32_t m1 = (c0 <= r0l + 8     ? 0x0000FFFFu : 0u) |
                                  (c0 + 1 <= r0l + 8 ? 0xFFFF0000u : 0u);
                    e01 &= m0; e23 &= m1;
                }
                pf01[nt] = e01; pf23[nt] = e23;
            }
            // ---- O += P @ V ; l += P @ ones (tensor-pipe row-sum) ----
#pragma unroll
            for (int kk = 0; kk < 4; kk++) {
                uint32_t af[4];
                af[0] = pf01[2 * kk];     af[1] = pf23[2 * kk];
                af[2] = pf01[2 * kk + 1]; af[3] = pf23[2 * kk + 1];
                mma16(lacc, af, ONESH2, ONESH2);
                const uint32_t vr = (uint32_t)(hl * 64 + kk * 16) + vrow;
#pragma unroll
                for (int p = 0; p < 4; p++) {
                    uint32_t vb[4];
                    ldm4t(vb, Vb + vr * 144u + (uint32_t)(p * 32) + vsel);
                    mma16(oacc[2 * p],     af, vb[0], vb[1]);
                    mma16(oacc[2 * p + 1], af, vb[2], vb[3]);
                }
            }
        }
    }

    // ---- epilogue: lacc[0]/lacc[2] hold complete row-sums in EVERY lane ----
    if (ns == 1) {
        const float inv0 = 1.0f / lacc[0];
        const float inv1 = 1.0f / lacc[2];
        float* og = outp + ((size_t)b * SEQ + qBase + r0l) * HDIM;
#pragma unroll
        for (int nt = 0; nt < 8; nt++) {
            int cc = nt * 8 + 2 * t4;
            float2 v0 = { oacc[nt][0] * inv0, oacc[nt][1] * inv0 };
            *reinterpret_cast<float2*>(og + cc) = v0;
            float2 v1 = { oacc[nt][2] * inv1, oacc[nt][3] * inv1 };
            *reinterpret_cast<float2*>(og + (size_t)8 * HDIM + cc) = v1;
        }
    } else {
        float* po = g_partO[s] + ((size_t)b * SEQ + qBase + r0l) * HDIM;
#pragma unroll
        for (int nt = 0; nt < 8; nt++) {
            int cc = nt * 8 + 2 * t4;
            float2 v0 = { oacc[nt][0], oacc[nt][1] };
            *reinterpret_cast<float2*>(po + cc) = v0;
            float2 v1 = { oacc[nt][2], oacc[nt][3] };
            *reinterpret_cast<float2*>(po + (size_t)8 * HDIM + cc) = v1;
        }
        if (t4 == 0) {
            g_partL[s][(size_t)b * SEQ + qBase + r0l]     = lacc[0];
            g_partL[s][(size_t)b * SEQ + qBase + r0l + 8] = lacc[2];
        }
    }
}

// ================= Kernel 3: combine splits (rows with qt >= 5 only) =================
// 8 batches x 1408 rows x 16 float4, 2 float4/thread -> 352 blocks.
__global__ void __launch_bounds__(256) combine_kernel(float* __restrict__ out)
{
    int base2 = (blockIdx.x * 256 + threadIdx.x) * 2;
    int bb  = base2 / 22528;                 // 1408 rows * 16 f4 per batch
    int rem = base2 - bb * 22528;
    int rowInB = 640 + (rem >> 4);
    int row = bb * SEQ + rowInB;
    int f4i = row * 16 + (rem & 15);
    int qt = rowInB >> 7;
    int ns = (qt + 5) / 5;                   // 2..4 here

    float4 o0 = reinterpret_cast<const float4*>(g_partO[0])[f4i];
    float4 o1 = reinterpret_cast<const float4*>(g_partO[0])[f4i + 1];
    float4 a0 = reinterpret_cast<const float4*>(g_partO[1])[f4i];
    float4 a1 = reinterpret_cast<const float4*>(g_partO[1])[f4i + 1];
    float  l  = g_partL[0][row] + g_partL[1][row];
    o0.x += a0.x; o0.y += a0.y; o0.z += a0.z; o0.w += a0.w;
    o1.x += a1.x; o1.y += a1.y; o1.z += a1.z; o1.w += a1.w;
#pragma unroll
    for (int s = 2; s < 4; s++) {
        if (ns > s) {
            float4 c0 = reinterpret_cast<const float4*>(g_partO[s])[f4i];
            float4 c1 = reinterpret_cast<const float4*>(g_partO[s])[f4i + 1];
            o0.x += c0.x; o0.y += c0.y; o0.z += c0.z; o0.w += c0.w;
            o1.x += c1.x; o1.y += c1.y; o1.z += c1.z; o1.w += c1.w;
            l += g_partL[s][row];
        }
    }
    float inv = 1.0f / l;
    o0.x *= inv; o0.y *= inv; o0.z *= inv; o0.w *= inv;
    o1.x *= inv; o1.y *= inv; o1.z *= inv; o1.w *= inv;
    reinterpret_cast<float4*>(out)[f4i]     = o0;
    reinterpret_cast<float4*>(out)[f4i + 1] = o1;
}

// ---------------- launch ----------------
extern "C" void kernel_launch(void* const* d_in, const int* in_sizes, int n_in,
                              void* d_out, int out_size)
{
    const float* x  = (const float*)d_in[0];
    const float* Wq = (const float*)d_in[1];
    const float* Wk = (const float*)d_in[2];
    const float* Wv = (const float*)d_in[3];
    float* out = (float*)d_out;

    wt_kernel<<<dim3(16, 3), 256>>>(Wq, Wk, Wv);

    cudaFuncSetAttribute(qkv_mma, cudaFuncAttributeMaxDynamicSharedMemorySize,
                         QKV_SMEM_BYTES);
    qkv_mma<<<(BATCH * SEQ) / 64, 256, QKV_SMEM_BYTES>>>(x);

    cudaFuncSetAttribute(attn_split, cudaFuncAttributeMaxDynamicSharedMemorySize,
                         ATTN_SMEM_BYTES);
    attn_split<<<272, 256, ATTN_SMEM_BYTES>>>(out);

    // rows with qt<5 were written directly by attn_split (ns==1)
    combine_kernel<<<352, 256>>>(out);
}

// round 17
// speedup vs baseline: 1.0309x; 1.0192x over previous
#include <cuda_runtime.h>
#include <cuda_fp16.h>
#include <cstdint>

#define BATCH 8
#define SEQ   2048
#define CDIM  1024
#define HDIM  64

// ---------------- persistent scratch ----------------
__device__ __half g_wth[3 * HDIM * CDIM];          // [192 n][1024 k] fp16 W^T
__device__ __half g_qh[BATCH * SEQ * HDIM];        // q PRE-SCALED by 0.125*log2(e)
__device__ __half g_kh[BATCH * SEQ * HDIM];
__device__ __half g_vh[BATCH * SEQ * HDIM];
__device__ float  g_partO[4][BATCH * SEQ * HDIM];
__device__ float  g_partL[4][BATCH * SEQ];

#define QSCALE 0.18033688011112042f   /* 0.125 * log2(e) */
#define ONESH2 0x3C003C00u            /* {1.0h, 1.0h}     */

// ---------------- helpers ----------------
__device__ __forceinline__ uint32_t smem_u32(const void* p) {
    uint32_t a;
    asm("{ .reg .u64 t; cvta.to.shared.u64 t, %1; cvt.u32.u64 %0, t; }" : "=r"(a) : "l"(p));
    return a;
}
__device__ __forceinline__ void cp16(uint32_t dst, const void* src) {
    asm volatile("cp.async.cg.shared.global [%0], [%1], 16;" :: "r"(dst), "l"(src));
}
#define CP_COMMIT asm volatile("cp.async.commit_group;" ::: "memory")
#define CP_WAIT0  asm volatile("cp.async.wait_group 0;" ::: "memory")
#define CP_WAIT1  asm volatile("cp.async.wait_group 1;" ::: "memory")

__device__ __forceinline__ uint32_t packh2(float lo, float hi) {
    uint32_t d;
    asm("cvt.rn.f16x2.f32 %0, %1, %2;" : "=r"(d) : "f"(hi), "f"(lo));
    return d;
}
__device__ __forceinline__ uint32_t ex2h2(uint32_t x) {
    uint32_t d;
    asm("ex2.approx.f16x2 %0, %1;" : "=r"(d) : "r"(x));
    return d;
}
// f32-accumulator HMMA
__device__ __forceinline__ void mma16(float* c, const uint32_t* a, uint32_t b0, uint32_t b1) {
    asm volatile(
        "mma.sync.aligned.m16n8k16.row.col.f32.f16.f16.f32 "
        "{%0,%1,%2,%3}, {%4,%5,%6,%7}, {%8,%9}, {%0,%1,%2,%3};"
        : "+f"(c[0]), "+f"(c[1]), "+f"(c[2]), "+f"(c[3])
        : "r"(a[0]), "r"(a[1]), "r"(a[2]), "r"(a[3]), "r"(b0), "r"(b1));
}
// f16-accumulator HMMA (half the accumulator traffic; output = packed h2)
__device__ __forceinline__ void mma16h(uint32_t* c, const uint32_t* a, uint32_t b0, uint32_t b1) {
    asm volatile(
        "mma.sync.aligned.m16n8k16.row.col.f16.f16.f16.f16 "
        "{%0,%1}, {%2,%3,%4,%5}, {%6,%7}, {%0,%1};"
        : "+r"(c[0]), "+r"(c[1])
        : "r"(a[0]), "r"(a[1]), "r"(a[2]), "r"(a[3]), "r"(b0), "r"(b1));
}
__device__ __forceinline__ void ldm4(uint32_t* r, uint32_t addr) {
    asm volatile("ldmatrix.sync.aligned.m8n8.x4.shared.b16 {%0,%1,%2,%3}, [%4];"
                 : "=r"(r[0]), "=r"(r[1]), "=r"(r[2]), "=r"(r[3]) : "r"(addr));
}
__device__ __forceinline__ void ldm4t(uint32_t* r, uint32_t addr) {
    asm volatile("ldmatrix.sync.aligned.m8n8.x4.trans.shared.b16 {%0,%1,%2,%3}, [%4];"
                 : "=r"(r[0]), "=r"(r[1]), "=r"(r[2]), "=r"(r[3]) : "r"(addr));
}

// ================= Kernel 0: W transpose + fp16 (MLP-optimized) =================
__global__ void __launch_bounds__(256) wt_kernel(const float* __restrict__ Wq,
                                                 const float* __restrict__ Wk,
                                                 const float* __restrict__ Wv)
{
    const int z = blockIdx.y;
    const float* W = (z == 0) ? Wq : (z == 1) ? Wk : Wv;
    __shared__ float tile[64][65];
    const int t = threadIdx.x;
    const int c0 = blockIdx.x * 64;

#pragma unroll
    for (int i = 0; i < 4; i++) {
        int idx = t + i * 256;
        int r = idx >> 4, q = idx & 15;
        float4 v = *reinterpret_cast<const float4*>(W + (size_t)(c0 + r) * HDIM + q * 4);
        tile[r][q * 4 + 0] = v.x; tile[r][q * 4 + 1] = v.y;
        tile[r][q * 4 + 2] = v.z; tile[r][q * 4 + 3] = v.w;
    }
    __syncthreads();

    __half* outp = g_wth + (size_t)z * HDIM * CDIM;
#pragma unroll
    for (int i = 0; i < 2; i++) {
        int idx = t + i * 256;
        int n = idx >> 3, cg = idx & 7;
        uint4 h;
        h.x = packh2(tile[cg * 8 + 0][n], tile[cg * 8 + 1][n]);
        h.y = packh2(tile[cg * 8 + 2][n], tile[cg * 8 + 3][n]);
        h.z = packh2(tile[cg * 8 + 4][n], tile[cg * 8 + 5][n]);
        h.w = packh2(tile[cg * 8 + 6][n], tile[cg * 8 + 7][n]);
        *reinterpret_cast<uint4*>(outp + (size_t)n * CDIM + c0 + cg * 8) = h;
    }
}

// ================= Kernel 1: fused QKV projection (2-stage) =================
// grid 256 x 256 thr, 2 CTAs/SM. 64-row M-tile, K-chunk 64.
// SMEM words: A0@0 A1@2304  B0@4608 B1@11520  -> 73728 B
#define QKV_SMEM_BYTES 73728

__global__ void __launch_bounds__(256, 2) qkv_mma(const float* __restrict__ x)
{
    extern __shared__ uint32_t smw[];
    const uint32_t sb = smem_u32(smw);
    const int t = threadIdx.x, lane = t & 31, warp = t >> 5;
    const int g = lane >> 2, t4 = lane & 3;
    const int wm = warp >> 2, wn = warp & 3;
    const int Mbase = blockIdx.x * 64;

    const uint32_t arow = lane & 15;
    const uint32_t asel = (uint32_t)((lane >> 4) << 4);
    const uint32_t nrow = (uint32_t)(((lane >> 4) << 3) + (lane & 7));
    const uint32_t bsel = (uint32_t)(((lane >> 3) & 1) << 4);

    float acc[2][6][4];
#pragma unroll
    for (int a = 0; a < 2; a++)
#pragma unroll
        for (int b = 0; b < 6; b++)
#pragma unroll
            for (int c = 0; c < 4; c++) acc[a][b][c] = 0.0f;

    const int xr = t >> 2, xj = t & 3;

    auto ldgX = [&](int c, float4* v) {
        const float* src = x + (size_t)(Mbase + xr) * CDIM + c * 64 + xj * 16;
#pragma unroll
        for (int i = 0; i < 4; i++) v[i] = *reinterpret_cast<const float4*>(src + i * 4);
    };
    auto stsX = [&](int st, const float4* v) {
        uint4 h0, h1;
        h0.x = packh2(v[0].x, v[0].y); h0.y = packh2(v[0].z, v[0].w);
        h0.z = packh2(v[1].x, v[1].y); h0.w = packh2(v[1].z, v[1].w);
        h1.x = packh2(v[2].x, v[2].y); h1.y = packh2(v[2].z, v[2].w);
        h1.z = packh2(v[3].x, v[3].y); h1.w = packh2(v[3].z, v[3].w);
        *reinterpret_cast<uint4*>(smw + st * 2304 + xr * 36 + xj * 8)     = h0;
        *reinterpret_cast<uint4*>(smw + st * 2304 + xr * 36 + xj * 8 + 4) = h1;
    };
    auto issueB = [&](int c, int st) {
        uint32_t bb = sb + (4608u + (uint32_t)st * 6912u) * 4u;
#pragma unroll
        for (int i = 0; i < 6; i++) {
            int idx = t + i * 256;
            int n = idx >> 3, j = idx & 7;
            cp16(bb + (uint32_t)(n * 36 + j * 4) * 4u,
                 g_wth + (size_t)n * CDIM + c * 64 + j * 8);
        }
    };

    float4 xa[4];
    ldgX(0, xa); stsX(0, xa);
    issueB(0, 0); CP_COMMIT;

    for (int c = 0; c < 16; c++) {
        const int st = c & 1;
        CP_WAIT0;
        __syncthreads();
        if (c < 15) { issueB(c + 1, st ^ 1); CP_COMMIT; ldgX(c + 1, xa); }

        const uint32_t Ab = sb + (uint32_t)st * 2304u * 4u;
        const uint32_t Bb = sb + (4608u + (uint32_t)st * 6912u) * 4u;

#pragma unroll
        for (int kk = 0; kk < 4; kk++) {
            uint32_t af0[4], af1[4];
            ldm4(af0, Ab + (wm * 32 +      arow) * 144u + kk * 32u + asel);
            ldm4(af1, Ab + (wm * 32 + 16 + arow) * 144u + kk * 32u + asel);
#pragma unroll
            for (int j = 0; j < 3; j++) {
                uint32_t bf[4];
                ldm4(bf, Bb + (wn * 48 + j * 16 + nrow) * 144u + kk * 32u + bsel);
                mma16(acc[0][2 * j],     af0, bf[0], bf[1]);
                mma16(acc[0][2 * j + 1], af0, bf[2], bf[3]);
                mma16(acc[1][2 * j],     af1, bf[0], bf[1]);
                mma16(acc[1][2 * j + 1], af1, bf[2], bf[3]);
            }
        }
        if (c < 15) stsX(st ^ 1, xa);
    }

#pragma unroll
    for (int mt = 0; mt < 2; mt++) {
        int r0 = Mbase + wm * 32 + mt * 16 + g;
#pragma unroll
        for (int nt = 0; nt < 6; nt++) {
            int ncol = wn * 48 + nt * 8 + 2 * t4;
            int w = ncol >> 6, cc = ncol & 63;
            __half* outp = (w == 0) ? g_qh : (w == 1) ? g_kh : g_vh;
            float sc = (w == 0) ? QSCALE : 1.0f;
            *reinterpret_cast<uint32_t*>(outp + (size_t)r0 * HDIM + cc) =
                packh2(acc[mt][nt][0] * sc, acc[mt][nt][1] * sc);
            *reinterpret_cast<uint32_t*>(outp + (size_t)(r0 + 8) * HDIM + cc) =
                packh2(acc[mt][nt][2] * sc, acc[mt][nt][3] * sc);
        }
    }
}

// ================= Kernel 2: split-K causal attention =================
// 272 CTAs, max 5 key-tile iters, one wave at 2 CTAs/SM.
// S-GEMM uses f16 accumulator (output = packed h2, direct ex2h2 input).
// SMEM words: K0@0 K1@4608 V0@9216 V1@13824 Q@18432 (each 4608) -> 92160 B
#define ATTN_SMEM_BYTES 92160

__global__ void __launch_bounds__(256, 2) attn_split(float* __restrict__ outp)
{
    extern __shared__ uint32_t smw[];
    const uint32_t sb = smem_u32(smw);
    const int t = threadIdx.x, lane = t & 31, warp = t >> 5;
    const int g = lane >> 2, t4 = lane & 3;

    const int bid = blockIdx.x;
    const int b = bid / 34, r = bid % 34;
    int qt, s, ns;
    if (r < 5)        { qt = r;                 s = 0;            ns = 1; }
    else if (r < 15)  { qt = 5 + (r - 5) / 2;   s = (r - 5) % 2;  ns = 2; }
    else if (r < 30)  { qt = 10 + (r - 15) / 3; s = (r - 15) % 3; ns = 3; }
    else              { qt = 15;                s = r - 30;       ns = 4; }
    const int len = qt + 1;
    const int k0t = s * len / ns, k1t = (s + 1) * len / ns;
    const int qBase = qt * 128;

    const __half* kg = g_kh + (size_t)b * SEQ * HDIM;
    const __half* vg = g_vh + (size_t)b * SEQ * HDIM;

    const uint32_t lrow8 = (uint32_t)(((lane >> 4) << 3) + (lane & 7));
    const uint32_t lsel  = (uint32_t)(((lane >> 3) & 1) << 4);
    const uint32_t vrow  = (uint32_t)((((lane >> 3) & 1) << 3) + (lane & 7));
    const uint32_t vsel  = (uint32_t)((lane >> 4) << 4);

    auto issueKV = [&](int kt, int st) {
        uint32_t kb = sb + (uint32_t)st * 4608u * 4u;
        uint32_t vb = sb + (9216u + (uint32_t)st * 4608u) * 4u;
#pragma unroll
        for (int i = 0; i < 4; i++) {
            int idx = t + i * 256;
            int rr = idx >> 3, j = idx & 7;
            cp16(kb + (uint32_t)(rr * 36 + j * 4) * 4u,
                 kg + (size_t)(kt * 128 + rr) * HDIM + j * 8);
            cp16(vb + (uint32_t)(rr * 36 + j * 4) * 4u,
                 vg + (size_t)(kt * 128 + rr) * HDIM + j * 8);
        }
    };

    issueKV(k0t, 0);
    {
        const __half* qg = g_qh + ((size_t)b * SEQ + qBase) * HDIM;
#pragma unroll
        for (int i = 0; i < 4; i++) {
            int idx = t + i * 256;
            int rr = idx >> 3, j = idx & 7;
            cp16(sb + (uint32_t)(18432 + rr * 36 + j * 4) * 4u,
                 qg + (size_t)rr * HDIM + j * 8);
        }
    }
    CP_COMMIT;
    CP_WAIT0;
    __syncthreads();

    uint32_t qf[4][4];
    {
        const uint32_t Qb = sb + 18432u * 4u;
        const uint32_t qrow = (uint32_t)(warp * 16 + (lane & 15));
        const uint32_t qsel = (uint32_t)((lane >> 4) << 4);
#pragma unroll
        for (int kk = 0; kk < 4; kk++) ldm4(qf[kk], Qb + qrow * 144u + kk * 32u + qsel);
    }

    float oacc[8][4];
#pragma unroll
    for (int a = 0; a < 8; a++)
#pragma unroll
        for (int c = 0; c < 4; c++) oacc[a][c] = 0.0f;
    float lacc[4] = {0.0f, 0.0f, 0.0f, 0.0f};
    const int r0l = warp * 16 + g;

    for (int kt = k0t; kt < k1t; kt++) {
        const int st = (kt - k0t) & 1;
        const bool more = (kt + 1 < k1t);
        if (kt > k0t) { CP_WAIT0; __syncthreads(); }
        if (more) { issueKV(kt + 1, st ^ 1); CP_COMMIT; }

        const uint32_t Kb = sb + (uint32_t)st * 4608u * 4u;
        const uint32_t Vb = sb + (9216u + (uint32_t)st * 4608u) * 4u;
        const bool dtile = (kt == qt);

#pragma unroll
        for (int hl = 0; hl < 2; hl++) {
            if (dtile && hl == 1 && warp < 4) continue;

            // ---- S = Qs @ K^T (64-key half), f16 accumulator, log2 domain ----
            uint32_t sacch[8][2];
#pragma unroll
            for (int a = 0; a < 8; a++) { sacch[a][0] = 0u; sacch[a][1] = 0u; }
#pragma unroll
            for (int p = 0; p < 4; p++) {
                const uint32_t krow = (uint32_t)(hl * 64 + p * 16) + lrow8;
#pragma unroll
                for (int kk = 0; kk < 4; kk++) {
                    uint32_t kb[4];
                    ldm4(kb, Kb + krow * 144u + kk * 32u + lsel);
                    mma16h(sacch[2 * p],     qf[kk], kb[0], kb[1]);
                    mma16h(sacch[2 * p + 1], qf[kk], kb[2], kb[3]);
                }
            }
            // ---- P = 2^S via f16x2 MUFU (acc already packed h2), mask ----
            uint32_t pf01[8], pf23[8];
#pragma unroll
            for (int nt = 0; nt < 8; nt++) {
                uint32_t e01 = ex2h2(sacch[nt][0]);
                uint32_t e23 = ex2h2(sacch[nt][1]);
                if (dtile) {
                    int c0 = hl * 64 + nt * 8 + 2 * t4;
                    uint32_t m0 = (c0 <= r0l      ? 0x0000FFFFu : 0u) |
                                  (c0 + 1 <= r0l  ? 0xFFFF0000u : 0u);
                    uint32_t m1 = (c0 <= r0l + 8     ? 0x0000FFFFu : 0u) |
                                  (c0 + 1 <= r0l + 8 ? 0xFFFF0000u : 0u);
                    e01 &= m0; e23 &= m1;
                }
                pf01[nt] = e01; pf23[nt] = e23;
            }
            // ---- O += P @ V ; l += P @ ones ----
#pragma unroll
            for (int kk = 0; kk < 4; kk++) {
                uint32_t af[4];
                af[0] = pf01[2 * kk];     af[1] = pf23[2 * kk];
                af[2] = pf01[2 * kk + 1]; af[3] = pf23[2 * kk + 1];
                mma16(lacc, af, ONESH2, ONESH2);
                const uint32_t vr = (uint32_t)(hl * 64 + kk * 16) + vrow;
#pragma unroll
                for (int p = 0; p < 4; p++) {
                    uint32_t vb[4];
                    ldm4t(vb, Vb + vr * 144u + (uint32_t)(p * 32) + vsel);
                    mma16(oacc[2 * p],     af, vb[0], vb[1]);
                    mma16(oacc[2 * p + 1], af, vb[2], vb[3]);
                }
            }
        }
    }

    // ---- epilogue ----
    if (ns == 1) {
        const float inv0 = 1.0f / lacc[0];
        const float inv1 = 1.0f / lacc[2];
        float* og = outp + ((size_t)b * SEQ + qBase + r0l) * HDIM;
#pragma unroll
        for (int nt = 0; nt < 8; nt++) {
            int cc = nt * 8 + 2 * t4;
            float2 v0 = { oacc[nt][0] * inv0, oacc[nt][1] * inv0 };
            *reinterpret_cast<float2*>(og + cc) = v0;
            float2 v1 = { oacc[nt][2] * inv1, oacc[nt][3] * inv1 };
            *reinterpret_cast<float2*>(og + (size_t)8 * HDIM + cc) = v1;
        }
    } else {
        float* po = g_partO[s] + ((size_t)b * SEQ + qBase + r0l) * HDIM;
#pragma unroll
        for (int nt = 0; nt < 8; nt++) {
            int cc = nt * 8 + 2 * t4;
            float2 v0 = { oacc[nt][0], oacc[nt][1] };
            *reinterpret_cast<float2*>(po + cc) = v0;
            float2 v1 = { oacc[nt][2], oacc[nt][3] };
            *reinterpret_cast<float2*>(po + (size_t)8 * HDIM + cc) = v1;
        }
        if (t4 == 0) {
            g_partL[s][(size_t)b * SEQ + qBase + r0l]     = lacc[0];
            g_partL[s][(size_t)b * SEQ + qBase + r0l + 8] = lacc[2];
        }
    }
}

// ================= Kernel 3: combine splits (rows with qt >= 5 only) =================
// 1 float4/thread, 704 blocks -> 180K threads for latency hiding.
__global__ void __launch_bounds__(256) combine_kernel(float* __restrict__ out)
{
    int idx = blockIdx.x * 256 + threadIdx.x;
    int bb  = idx / 22528;                   // 1408 rows * 16 f4 per batch
    int rem = idx - bb * 22528;
    int rowInB = 640 + (rem >> 4);
    int row = bb * SEQ + rowInB;
    int f4i = row * 16 + (rem & 15);
    int qt = rowInB >> 7;
    int ns = (qt + 5) / 5;                   // 2..4 here

    float4 o0 = reinterpret_cast<const float4*>(g_partO[0])[f4i];
    float4 a0 = reinterpret_cast<const float4*>(g_partO[1])[f4i];
    float  l  = g_partL[0][row] + g_partL[1][row];
    o0.x += a0.x; o0.y += a0.y; o0.z += a0.z; o0.w += a0.w;
#pragma unroll
    for (int s = 2; s < 4; s++) {
        if (ns > s) {
            float4 c0 = reinterpret_cast<const float4*>(g_partO[s])[f4i];
            o0.x += c0.x; o0.y += c0.y; o0.z += c0.z; o0.w += c0.w;
            l += g_partL[s][row];
        }
    }
    float inv = 1.0f / l;
    o0.x *= inv; o0.y *= inv; o0.z *= inv; o0.w *= inv;
    reinterpret_cast<float4*>(out)[f4i] = o0;
}

// ---------------- launch ----------------
extern "C" void kernel_launch(void* const* d_in, const int* in_sizes, int n_in,
                              void* d_out, int out_size)
{
    const float* x  = (const float*)d_in[0];
    const float* Wq = (const float*)d_in[1];
    const float* Wk = (const float*)d_in[2];
    const float* Wv = (const float*)d_in[3];
    float* out = (float*)d_out;

    wt_kernel<<<dim3(16, 3), 256>>>(Wq, Wk, Wv);

    cudaFuncSetAttribute(qkv_mma, cudaFuncAttributeMaxDynamicSharedMemorySize,
                         QKV_SMEM_BYTES);
    qkv_mma<<<(BATCH * SEQ) / 64, 256, QKV_SMEM_BYTES>>>(x);

    cudaFuncSetAttribute(attn_split, cudaFuncAttributeMaxDynamicSharedMemorySize,
                         ATTN_SMEM_BYTES);
    attn_split<<<272, 256, ATTN_SMEM_BYTES>>>(out);

    // rows with qt<5 were written directly by attn_split (ns==1)
    combine_kernel<<<704, 256>>>(out);
}